// round 5
// baseline (speedup 1.0000x reference)
#include <cuda_runtime.h>

#define NPTS 4096
#define NB   8
#define CDIM 32
#define KOUT 9
#define KALL 18
#define MT   128
#define WARPS 8
#define NTHREADS 256

// ---------------------------------------------------------------------------
// One warp per query row. Candidates staged through a shared tile reused by
// all 8 warps of the block. Each lane keeps a threshold-guarded sorted top-18
// of its own candidate subset (m = m0 + j*32 + lane, ascending m per lane);
// final per-warp merge is an 18-step lexicographic (dist, idx) argmin, which
// reproduces jax top_k's ascending-distance, lower-index-first-on-ties order.
// Output written as float32 (declared output dtype; indices are exactly
// representable).
// ---------------------------------------------------------------------------
__global__ __launch_bounds__(NTHREADS)
void knn_simple(const float* __restrict__ x, float* __restrict__ out) {
    __shared__ float pt[CDIM][MT];

    const int b    = blockIdx.y;
    const int tid  = threadIdx.x;
    const int wid  = tid >> 5;
    const int lane = tid & 31;
    const int n    = blockIdx.x * WARPS + wid;
    const float* xb = x + (size_t)b * CDIM * NPTS;

    // query vector for this warp's row (warp-uniform broadcast loads)
    float q[CDIM];
#pragma unroll
    for (int c = 0; c < CDIM; c++) q[c] = xb[c * NPTS + n];

    // per-lane sorted top-18 (ascending distance)
    float ld[KALL];
    int   li[KALL];
#pragma unroll
    for (int j = 0; j < KALL; j++) { ld[j] = 3.4e38f; li[j] = 0x7FFFFFFF; }
    float thr = 3.4e38f;

    for (int m0 = 0; m0 < NPTS; m0 += MT) {
        __syncthreads();
        // cooperative coalesced tile load: pt[c][ml] = x[b][c][m0+ml]
#pragma unroll
        for (int k = 0; k < (CDIM * MT) / NTHREADS; k++) {
            int idx = k * NTHREADS + tid;
            pt[idx >> 7][idx & (MT - 1)] = xb[(idx >> 7) * NPTS + m0 + (idx & (MT - 1))];
        }
        __syncthreads();

        for (int j = 0; j < MT / 32; j++) {
            int ml = j * 32 + lane;
            float acc = 0.f;
#pragma unroll
            for (int c = 0; c < CDIM; c++) {
                float t = q[c] - pt[c][ml];   // conflict-free: lanes consecutive
                acc = fmaf(t, t, acc);
            }
            if (acc < thr) {  // strict '<': ties keep earlier (lower) index
                int p = KALL - 1;
                while (p > 0 && acc < ld[p - 1]) {
                    ld[p] = ld[p - 1];
                    li[p] = li[p - 1];
                    p--;
                }
                ld[p] = acc;
                li[p] = m0 + ml;
                thr = ld[KALL - 1];
            }
        }
    }

    // ---- warp merge: 18 rounds of lexicographic (dist, idx) argmin ----
    int res[KALL];
    int ptr = 0;
    for (int t = 0; t < KALL; t++) {
        float d  = 3.4e38f;
        int   id = 0x7FFFFFFF;
        if (ptr < KALL) { d = ld[ptr]; id = li[ptr]; }
        float bd = d;
        int   bi = id;
#pragma unroll
        for (int off = 16; off; off >>= 1) {
            float od = __shfl_down_sync(0xFFFFFFFFu, bd, off);
            int   oi = __shfl_down_sync(0xFFFFFFFFu, bi, off);
            if (od < bd || (od == bd && oi < bi)) { bd = od; bi = oi; }
        }
        bd = __shfl_sync(0xFFFFFFFFu, bd, 0);
        bi = __shfl_sync(0xFFFFFFFFu, bi, 0);
        if (ptr < KALL && d == bd && id == bi) ptr++;  // unique winner advances
        res[t] = bi;
    }

    // ---- output (float32): out[0,b,n,j] = res[2j], out[1,b,n,j] = n ----
    if (lane == 0) {
        int base0 = (b * NPTS + n) * KOUT;
        int base1 = ((NB + b) * NPTS + n) * KOUT;
#pragma unroll
        for (int jj = 0; jj < KOUT; jj++) {
            out[base0 + jj] = (float)res[2 * jj];
            out[base1 + jj] = (float)n;
        }
    }
}

extern "C" void kernel_launch(void* const* d_in, const int* in_sizes, int n_in,
                              void* d_out, int out_size) {
    const float* x = (const float*)d_in[0];
    float* out = (float*)d_out;
    dim3 grid(NPTS / WARPS, NB);
    knn_simple<<<grid, NTHREADS>>>(x, out);
}

// round 6
// speedup vs baseline: 4.8247x; 4.8247x over previous
#include <cuda_runtime.h>

#define NPTS 4096
#define NB   8
#define CDIM 32
#define KOUT 9
#define KALL 18
#define TS   64
#define NTHREADS 256

__device__ float g_sq[NB * NPTS];

// ---------------------------------------------------------------------------
// squared norms per point (matches reference sum over C)
// ---------------------------------------------------------------------------
__global__ void sqnorm_kernel(const float* __restrict__ x) {
    int idx = blockIdx.x * blockDim.x + threadIdx.x;
    if (idx >= NB * NPTS) return;
    int b = idx >> 12;
    int n = idx & (NPTS - 1);
    const float* p = x + (size_t)b * CDIM * NPTS + n;
    float s = 0.f;
#pragma unroll
    for (int c = 0; c < CDIM; c++) {
        float v = p[c * NPTS];
        s = fmaf(v, v, s);
    }
    g_sq[idx] = s;
}

// ---------------------------------------------------------------------------
// 64x64 distance tiles + exact per-row top-18 (static shared only).
//  - 16x16 threads, 4x4 register fragments -> 16 independent FMA chains per
//    thread (issue-bound, not latency-bound)
//  - distance d = (rn - 2*inner) + cn, same formula as the reference
//  - distance tile in smem with 16-chunk XOR swizzle:
//      physical_chunk = logical_chunk ^ (row & 15)  (conflict-free STS/LDS.128)
//  - threads 0..63 scan their own row; private sorted top-18 list in smem
//    behind a register threshold; ascending-m + strict '<' preserves
//    jax top_k tie order (lower index first)
// ---------------------------------------------------------------------------
__global__ __launch_bounds__(NTHREADS)
void knn_kernel(const float* __restrict__ x, float* __restrict__ out) {
    __shared__ __align__(16) float qt[CDIM][TS];
    __shared__ __align__(16) float pt[CDIM][TS];
    __shared__ __align__(16) float dt[TS][TS];
    __shared__ float rn[TS];
    __shared__ float cn[TS];
    __shared__ float ld[TS][KALL];
    __shared__ int   li[TS][KALL];

    const int b    = blockIdx.y;
    const int row0 = blockIdx.x * TS;
    const int tid  = threadIdx.x;
    const int tx   = tid & 15;
    const int ty   = tid >> 4;
    const float* xb = x + (size_t)b * CDIM * NPTS;

    // load query tile: qt[c][r] = x[b][c][row0+r]
#pragma unroll
    for (int k = 0; k < (CDIM * TS) / NTHREADS; k++) {
        int idx = k * NTHREADS + tid;
        qt[idx >> 6][idx & 63] = xb[(idx >> 6) * NPTS + row0 + (idx & 63)];
    }
    if (tid < TS) {
        rn[tid] = g_sq[b * NPTS + row0 + tid];
#pragma unroll
        for (int j = 0; j < KALL; j++) ld[tid][j] = 3.4e38f;
    }
    float thr = 3.4e38f;  // running 18th-smallest (scan threads only)
    __syncthreads();

    for (int m0 = 0; m0 < NPTS; m0 += TS) {
        // ---- candidate tile ----
#pragma unroll
        for (int k = 0; k < (CDIM * TS) / NTHREADS; k++) {
            int idx = k * NTHREADS + tid;
            pt[idx >> 6][idx & 63] = xb[(idx >> 6) * NPTS + m0 + (idx & 63)];
        }
        if (tid < TS) cn[tid] = g_sq[b * NPTS + m0 + tid];
        __syncthreads();

        // ---- 64x64x32 inner products, 4x4 per thread ----
        float acc[4][4];
#pragma unroll
        for (int i = 0; i < 4; i++)
#pragma unroll
            for (int j = 0; j < 4; j++) acc[i][j] = 0.f;

#pragma unroll 8
        for (int c = 0; c < CDIM; c++) {
            float4 q = *(const float4*)&qt[c][4 * ty];
            float4 p = *(const float4*)&pt[c][4 * tx];
            float qv[4] = {q.x, q.y, q.z, q.w};
            float pv[4] = {p.x, p.y, p.z, p.w};
#pragma unroll
            for (int i = 0; i < 4; i++)
#pragma unroll
                for (int j = 0; j < 4; j++)
                    acc[i][j] = fmaf(qv[i], pv[j], acc[i][j]);
        }

        // ---- epilogue: d = (rn - 2*acc) + cn, swizzled float4 store ----
        float c0 = cn[4 * tx + 0];
        float c1 = cn[4 * tx + 1];
        float c2 = cn[4 * tx + 2];
        float c3 = cn[4 * tx + 3];
#pragma unroll
        for (int i = 0; i < 4; i++) {
            int r = 4 * ty + i;
            float rni = rn[r];
            float4 v;
            v.x = (rni - 2.f * acc[i][0]) + c0;
            v.y = (rni - 2.f * acc[i][1]) + c1;
            v.z = (rni - 2.f * acc[i][2]) + c2;
            v.w = (rni - 2.f * acc[i][3]) + c3;
            ((float4*)dt[r])[tx ^ (r & 15)] = v;
        }
        __syncthreads();

        // ---- per-row scan + sorted insert (threads 0..63) ----
        if (tid < TS) {
            const int sw = tid & 15;
            const float4* dtr = (const float4*)dt[tid];
#pragma unroll 4
            for (int l = 0; l < 16; l++) {
                float4 v = dtr[l ^ sw];
                int mb = m0 + 4 * l;
                float dv[4] = {v.x, v.y, v.z, v.w};
#pragma unroll
                for (int e = 0; e < 4; e++) {
                    float d = dv[e];
                    if (d < thr) {  // strict: ties keep earlier (lower) index
                        int j = KALL - 1;
                        while (j > 0 && d < ld[tid][j - 1]) {
                            ld[tid][j] = ld[tid][j - 1];
                            li[tid][j] = li[tid][j - 1];
                            j--;
                        }
                        ld[tid][j] = d;
                        li[tid][j] = mb + e;
                        thr = ld[tid][KALL - 1];
                    }
                }
            }
        }
        __syncthreads();
    }

    // ---- output (float32): out[0,b,n,j] = nn_idx, out[1,b,n,j] = n ----
    if (tid < TS) {
        int n = row0 + tid;
        int base0 = (b * NPTS + n) * KOUT;
        int base1 = ((NB + b) * NPTS + n) * KOUT;
#pragma unroll
        for (int j = 0; j < KOUT; j++) {
            out[base0 + j] = (float)li[tid][2 * j];
            out[base1 + j] = (float)n;
        }
    }
}

extern "C" void kernel_launch(void* const* d_in, const int* in_sizes, int n_in,
                              void* d_out, int out_size) {
    const float* x = (const float*)d_in[0];
    float* out = (float*)d_out;

    sqnorm_kernel<<<(NB * NPTS + 255) / 256, 256>>>(x);

    dim3 grid(NPTS / TS, NB);
    knn_kernel<<<grid, NTHREADS>>>(x, out);
}

// round 7
// speedup vs baseline: 4.9717x; 1.0305x over previous
#include <cuda_runtime.h>

#define NPTS  4096
#define NB    8
#define CDIM  32
#define KOUT  9
#define KALL  18
#define TILE  128
#define NTHREADS 256

// shared memory layout (float offsets)
#define SM_QT 0
#define SM_PT (SM_QT + CDIM*TILE)          // 4096
#define SM_DT (SM_PT + CDIM*TILE)          // 8192
#define SM_RN (SM_DT + TILE*TILE)          // 24576
#define SM_CN (SM_RN + TILE)               // 24704
#define SM_LD (SM_CN + TILE)               // 24832
#define SM_LI (SM_LD + TILE*KALL)          // 27136 (shorts region)
#define SMEM_FLOATS (SM_LI + (TILE*KALL)/2)
#define SMEM_BYTES  (SMEM_FLOATS * 4)      // 113,152 bytes -> 2 blocks/SM

__device__ float g_sq[NB * NPTS];

// ---------------------------------------------------------------------------
// squared norms per point (matches reference sum over C)
// ---------------------------------------------------------------------------
__global__ void sqnorm_kernel(const float* __restrict__ x) {
    int idx = blockIdx.x * blockDim.x + threadIdx.x;
    if (idx >= NB * NPTS) return;
    int b = idx >> 12;
    int n = idx & (NPTS - 1);
    const float* p = x + (size_t)(b * CDIM) * NPTS + n;
    float s = 0.f;
#pragma unroll
    for (int c = 0; c < CDIM; c++) {
        float v = p[c * NPTS];
        s = fmaf(v, v, s);
    }
    g_sq[idx] = s;
}

// ---------------------------------------------------------------------------
// 128x128 distance tiles + exact per-row top-18.
//  - 16x16 threads, 8x8 register fragments (4+4 split) -> 64 independent FMA
//    chains per thread; all LDS.128 conflict-free
//  - distance d = (rn - 2*inner) + cn  (identical to reference arithmetic)
//  - dt stored with 32-chunk XOR swizzle: phys_chunk = logical ^ (row & 31)
//  - threads 0..127 scan their own row; sorted top-18 (dist in smem floats,
//    idx in smem shorts) behind a register threshold; ascending-m strict '<'
//    insert preserves jax top_k tie order (lower index first)
// ---------------------------------------------------------------------------
__global__ __launch_bounds__(NTHREADS, 2)
void knn_kernel(const float* __restrict__ x, float* __restrict__ out) {
    extern __shared__ float sm[];
    float* qt = sm + SM_QT;   // [c][row]   32x128
    float* pt = sm + SM_PT;   // [c][cand]  32x128
    float* dt = sm + SM_DT;   // [row][cand] 128x128, chunk-swizzled
    float* rn = sm + SM_RN;   // row norms
    float* cn = sm + SM_CN;   // cand norms
    float* ld = sm + SM_LD;   // top-18 distances per row
    short* li = (short*)(sm + SM_LI); // top-18 indices per row

    const int b    = blockIdx.y;
    const int row0 = blockIdx.x * TILE;
    const int tid  = threadIdx.x;
    const int tx   = tid & 15;
    const int ty   = tid >> 4;
    const float* xb = x + (size_t)(b * CDIM) * NPTS;

    // load query tile (coalesced: 128 consecutive floats per c-row)
#pragma unroll
    for (int k = 0; k < (CDIM * TILE) / NTHREADS; k++) {
        int idx = k * NTHREADS + tid;
        qt[idx] = xb[(idx >> 7) * NPTS + row0 + (idx & 127)];
    }
    if (tid < TILE) {
        rn[tid] = g_sq[b * NPTS + row0 + tid];
#pragma unroll
        for (int j = 0; j < KALL; j++) ld[tid * KALL + j] = 3.4e38f;
    }
    float thr = 3.4e38f;  // running 18th-smallest (scan threads only)
    __syncthreads();

    for (int m0 = 0; m0 < NPTS; m0 += TILE) {
        // ---- candidate tile ----
#pragma unroll
        for (int k = 0; k < (CDIM * TILE) / NTHREADS; k++) {
            int idx = k * NTHREADS + tid;
            pt[idx] = xb[(idx >> 7) * NPTS + m0 + (idx & 127)];
        }
        if (tid < TILE) cn[tid] = g_sq[b * NPTS + m0 + tid];
        __syncthreads();

        // ---- 128x128x32 inner products, 8x8 per thread ----
        float acc[8][8];
#pragma unroll
        for (int i = 0; i < 8; i++)
#pragma unroll
            for (int j = 0; j < 8; j++) acc[i][j] = 0.f;

#pragma unroll 4
        for (int c = 0; c < CDIM; c++) {
            float4 qa = *(const float4*)(qt + c * TILE + 4 * ty);
            float4 qb = *(const float4*)(qt + c * TILE + 64 + 4 * ty);
            float4 pa = *(const float4*)(pt + c * TILE + 4 * tx);
            float4 pb = *(const float4*)(pt + c * TILE + 64 + 4 * tx);
            float qv[8] = {qa.x, qa.y, qa.z, qa.w, qb.x, qb.y, qb.z, qb.w};
            float pv[8] = {pa.x, pa.y, pa.z, pa.w, pb.x, pb.y, pb.z, pb.w};
#pragma unroll
            for (int i = 0; i < 8; i++)
#pragma unroll
                for (int j = 0; j < 8; j++)
                    acc[i][j] = fmaf(qv[i], pv[j], acc[i][j]);
        }

        // ---- epilogue: d = (rn - 2*acc) + cn, swizzled float4 stores ----
        float cnv[8];
#pragma unroll
        for (int j = 0; j < 8; j++)
            cnv[j] = cn[(j < 4) ? (4 * tx + j) : (60 + 4 * tx + j)];

#pragma unroll
        for (int i = 0; i < 8; i++) {
            int r = (i < 4) ? (4 * ty + i) : (60 + 4 * ty + i);
            float rni = rn[r];
            float4 v0, v1;
            v0.x = (rni - 2.f * acc[i][0]) + cnv[0];
            v0.y = (rni - 2.f * acc[i][1]) + cnv[1];
            v0.z = (rni - 2.f * acc[i][2]) + cnv[2];
            v0.w = (rni - 2.f * acc[i][3]) + cnv[3];
            v1.x = (rni - 2.f * acc[i][4]) + cnv[4];
            v1.y = (rni - 2.f * acc[i][5]) + cnv[5];
            v1.z = (rni - 2.f * acc[i][6]) + cnv[6];
            v1.w = (rni - 2.f * acc[i][7]) + cnv[7];
            int sw = r & 31;
            float4* dtr = (float4*)dt + r * 32;
            dtr[tx ^ sw]        = v0;
            dtr[(16 + tx) ^ sw] = v1;
        }
        __syncthreads();

        // ---- per-row scan + sorted insert (threads 0..127) ----
        if (tid < TILE) {
            const int r = tid;
            const int sw = r & 31;
            const float4* dtr = (const float4*)dt + r * 32;
            float* lr = ld + r * KALL;
            short* lir = li + r * KALL;
#pragma unroll 4
            for (int l = 0; l < 32; l++) {
                float4 v = dtr[l ^ sw];
                int mb = m0 + 4 * l;
                float dv[4] = {v.x, v.y, v.z, v.w};
#pragma unroll
                for (int e = 0; e < 4; e++) {
                    float d = dv[e];
                    if (d < thr) {  // strict: ties keep earlier (lower) index
                        int j = KALL - 1;
                        while (j > 0 && d < lr[j - 1]) {
                            lr[j] = lr[j - 1];
                            lir[j] = lir[j - 1];
                            j--;
                        }
                        lr[j] = d;
                        lir[j] = (short)(mb + e);
                        thr = lr[KALL - 1];
                    }
                }
            }
        }
        __syncthreads();
    }

    // ---- output (float32): out[0,b,n,j] = nn_idx, out[1,b,n,j] = n ----
    if (tid < TILE) {
        int n = row0 + tid;
        const short* lir = li + tid * KALL;
        int base0 = (b * NPTS + n) * KOUT;
        int base1 = ((NB + b) * NPTS + n) * KOUT;
#pragma unroll
        for (int j = 0; j < KOUT; j++) {
            out[base0 + j] = (float)lir[2 * j];
            out[base1 + j] = (float)n;
        }
    }
}

extern "C" void kernel_launch(void* const* d_in, const int* in_sizes, int n_in,
                              void* d_out, int out_size) {
    const float* x = (const float*)d_in[0];
    float* out = (float*)d_out;

    cudaFuncSetAttribute(knn_kernel, cudaFuncAttributeMaxDynamicSharedMemorySize,
                         SMEM_BYTES);

    sqnorm_kernel<<<(NB * NPTS + 255) / 256, 256>>>(x);

    dim3 grid(NPTS / TILE, NB);
    knn_kernel<<<grid, NTHREADS, SMEM_BYTES>>>(x, out);
}

// round 8
// speedup vs baseline: 6.1381x; 1.2346x over previous
#include <cuda_runtime.h>

#define NPTS  4096
#define NB    8
#define CDIM  32
#define KOUT  9
#define KALL  18
#define TILE  128
#define NTHREADS 512

// shared memory layout (float offsets)
#define SM_QT 0
#define SM_PT (SM_QT + CDIM*TILE)          // 4096
#define SM_DT (SM_PT + CDIM*TILE)          // 8192
#define SM_RN (SM_DT + TILE*TILE)          // 24576
#define SM_CN (SM_RN + TILE)               // 24704
#define SMEM_FLOATS (SM_CN + TILE)         // 24832
#define SMEM_BYTES  (SMEM_FLOATS * 4)      // 99,328 bytes

__device__ float g_sq[NB * NPTS];

__global__ void sqnorm_kernel(const float* __restrict__ x) {
    int idx = blockIdx.x * blockDim.x + threadIdx.x;
    if (idx >= NB * NPTS) return;
    int b = idx >> 12;
    int n = idx & (NPTS - 1);
    const float* p = x + (size_t)(b * CDIM) * NPTS + n;
    float s = 0.f;
#pragma unroll
    for (int c = 0; c < CDIM; c++) {
        float v = p[c * NPTS];
        s = fmaf(v, v, s);
    }
    g_sq[idx] = s;
}

// ---------------------------------------------------------------------------
// 128x128 tiles, 512 threads:
//  - compute: 32x16 thread grid, 4x8 fragments (32 indep FMA chains, ~100 regs)
//  - scan: EVERY thread owns a quarter-row (row = tid>>2, 32 cands/tile),
//    register-resident top-18 via branch-free unrolled predicated shifts
//  - end: 4-way lexicographic (d, idx) merge per row == jax top_k order
// ---------------------------------------------------------------------------
__global__ __launch_bounds__(NTHREADS, 1)
void knn_kernel(const float* __restrict__ x, float* __restrict__ out) {
    extern __shared__ float sm[];
    float* qt = sm + SM_QT;
    float* pt = sm + SM_PT;
    float* dt = sm + SM_DT;   // 128x128, chunk-swizzled; reused for merge
    float* rn = sm + SM_RN;
    float* cn = sm + SM_CN;

    const int b    = blockIdx.y;
    const int row0 = blockIdx.x * TILE;
    const int tid  = threadIdx.x;
    const int tx   = tid & 15;          // 16 column-groups (8 cols: 4tx, 64+4tx)
    const int ty   = tid >> 4;          // 32 row-groups (rows 4ty..4ty+3)
    const float* xb = x + (size_t)(b * CDIM) * NPTS;

    const int srow = tid >> 2;          // scan row
    const int sq   = tid & 3;           // scan quarter
    const int ssw  = srow & 31;

    // register top-18 for this thread's quarter-row
    float dl[KALL];
    int   il[KALL];
#pragma unroll
    for (int j = 0; j < KALL; j++) { dl[j] = 3.4e38f; il[j] = 0x7FFFFFFF; }

    // query tile
#pragma unroll
    for (int k = 0; k < (CDIM * TILE) / NTHREADS; k++) {
        int idx = k * NTHREADS + tid;
        qt[idx] = xb[(idx >> 7) * NPTS + row0 + (idx & 127)];
    }
    if (tid < TILE) rn[tid] = g_sq[b * NPTS + row0 + tid];
    __syncthreads();

    for (int m0 = 0; m0 < NPTS; m0 += TILE) {
        // candidate tile
#pragma unroll
        for (int k = 0; k < (CDIM * TILE) / NTHREADS; k++) {
            int idx = k * NTHREADS + tid;
            pt[idx] = xb[(idx >> 7) * NPTS + m0 + (idx & 127)];
        }
        if (tid < TILE) cn[tid] = g_sq[b * NPTS + m0 + tid];
        __syncthreads();

        // ---- 128x128x32 inner products, 4x8 per thread ----
        float acc[4][8];
#pragma unroll
        for (int i = 0; i < 4; i++)
#pragma unroll
            for (int j = 0; j < 8; j++) acc[i][j] = 0.f;

#pragma unroll 2
        for (int c = 0; c < CDIM; c++) {
            float4 q  = *(const float4*)(qt + c * TILE + 4 * ty);
            float4 pa = *(const float4*)(pt + c * TILE + 4 * tx);
            float4 pb = *(const float4*)(pt + c * TILE + 64 + 4 * tx);
            float qv[4] = {q.x, q.y, q.z, q.w};
            float pv[8] = {pa.x, pa.y, pa.z, pa.w, pb.x, pb.y, pb.z, pb.w};
#pragma unroll
            for (int i = 0; i < 4; i++)
#pragma unroll
                for (int j = 0; j < 8; j++)
                    acc[i][j] = fmaf(qv[i], pv[j], acc[i][j]);
        }

        // ---- epilogue: d = (rn - 2*acc) + cn, swizzled float4 stores ----
        float cnv[8];
#pragma unroll
        for (int j = 0; j < 8; j++)
            cnv[j] = cn[(j < 4) ? (4 * tx + j) : (60 + 4 * tx + j)];

#pragma unroll
        for (int i = 0; i < 4; i++) {
            int r = 4 * ty + i;
            float rni = rn[r];
            float4 v0, v1;
            v0.x = (rni - 2.f * acc[i][0]) + cnv[0];
            v0.y = (rni - 2.f * acc[i][1]) + cnv[1];
            v0.z = (rni - 2.f * acc[i][2]) + cnv[2];
            v0.w = (rni - 2.f * acc[i][3]) + cnv[3];
            v1.x = (rni - 2.f * acc[i][4]) + cnv[4];
            v1.y = (rni - 2.f * acc[i][5]) + cnv[5];
            v1.z = (rni - 2.f * acc[i][6]) + cnv[6];
            v1.w = (rni - 2.f * acc[i][7]) + cnv[7];
            int sw = r & 31;
            float4* dtr = (float4*)dt + r * 32;
            dtr[tx ^ sw]        = v0;
            dtr[(16 + tx) ^ sw] = v1;
        }
        __syncthreads();

        // ---- quarter-row scan: 8 float4 chunks, register insert ----
        {
            const float4* dtr = (const float4*)dt + srow * 32;
            float thr = dl[KALL - 1];
#pragma unroll
            for (int l = 0; l < 8; l++) {
                float4 v = dtr[(sq * 8 + l) ^ ssw];
                int mb = m0 + sq * 32 + 4 * l;
                float dv[4] = {v.x, v.y, v.z, v.w};
#pragma unroll
                for (int e = 0; e < 4; e++) {
                    float d = dv[e];
                    if (d < thr) {
                        int mi = mb + e;
                        // branch-free sorted insert (ties: after equals ->
                        // lower index first, since m ascends per quarter)
#pragma unroll
                        for (int j = KALL - 1; j >= 1; j--) {
                            bool sh = d < dl[j - 1];
                            bool pl = !sh && (d < dl[j]);
                            float pd = dl[j - 1]; int pi = il[j - 1];
                            dl[j] = sh ? pd : (pl ? d  : dl[j]);
                            il[j] = sh ? pi : (pl ? mi : il[j]);
                        }
                        if (d < dl[0]) { dl[0] = d; il[0] = mi; }
                        thr = dl[KALL - 1];
                    }
                }
            }
        }
        __syncthreads();
    }

    // ---- dump quarter lists into dt region, then 4-way merge per row ----
    float* sd = dt;                       // 512*18 floats
    short* si = (short*)(dt + NTHREADS * KALL);
#pragma unroll
    for (int j = 0; j < KALL; j++) {
        sd[tid * KALL + j] = dl[j];
        si[tid * KALL + j] = (short)il[j];
    }
    __syncthreads();

    if (tid < TILE) {
        int cur[4] = {0, 0, 0, 0};
        int n = row0 + tid;
        int base0 = (b * NPTS + n) * KOUT;
        int base1 = ((NB + b) * NPTS + n) * KOUT;
#pragma unroll
        for (int t = 0; t < KALL; t++) {
            float bd = 3.5e38f;
            int   bi = 0x7FFFFFFF;
            int   bq = 0;
#pragma unroll
            for (int q = 0; q < 4; q++) {
                int c = cur[q];
                float d2 = sd[(tid * 4 + q) * KALL + c];
                int   i2 = (int)si[(tid * 4 + q) * KALL + c];
                if (d2 < bd || (d2 == bd && i2 < bi)) { bd = d2; bi = i2; bq = q; }
            }
            cur[bq]++;
            if ((t & 1) == 0) out[base0 + (t >> 1)] = (float)bi;
        }
#pragma unroll
        for (int j = 0; j < KOUT; j++) out[base1 + j] = (float)n;
    }
}

extern "C" void kernel_launch(void* const* d_in, const int* in_sizes, int n_in,
                              void* d_out, int out_size) {
    const float* x = (const float*)d_in[0];
    float* out = (float*)d_out;

    cudaFuncSetAttribute(knn_kernel, cudaFuncAttributeMaxDynamicSharedMemorySize,
                         SMEM_BYTES);

    sqnorm_kernel<<<(NB * NPTS + 511) / 512, 512>>>(x);

    dim3 grid(NPTS / TILE, NB);
    knn_kernel<<<grid, NTHREADS, SMEM_BYTES>>>(x, out);
}